// round 2
// baseline (speedup 1.0000x reference)
#include <cuda_runtime.h>

// ---------------------------------------------------------------------------
// MultiHeadSelfAttention: B=128,H=128,F=8,D=200, nh=10, hd=20
// x flat: (131072, 200). Q=XWq, K=XWk, V=XWv (each 131072x200).
// Per (i in 1024, h in 10): rows i*128..i*128+127, cols h*20..h*20+19.
// scores = qk^T/sqrt(20); softmax; attn -> d_out[0:167772160]
// ctx = attn @ v (flat 131072x200); out = ctx @ Wq -> d_out[167772160:]
// ---------------------------------------------------------------------------

#define M_ROWS 131072L
#define DPAD 202            // x-tile pitch: even (8B-aligned LDS.64 pairs)

typedef unsigned long long u64;

__device__ __forceinline__ u64 pk2(float lo, float hi) {
    u64 r; asm("mov.b64 %0, {%1,%2};" : "=l"(r) : "f"(lo), "f"(hi)); return r;
}
__device__ __forceinline__ void upk2(float& lo, float& hi, u64 v) {
    asm("mov.b64 {%0,%1}, %2;" : "=f"(lo), "=f"(hi) : "l"(v));
}
// Packed fp32x2 FMA — 2 MACs per instruction on the Blackwell fp32 pipe.
__device__ __forceinline__ u64 ffma2(u64 a, u64 b, u64 c) {
    u64 d; asm("fma.rn.f32x2 %0, %1, %2, %3;" : "=l"(d) : "l"(a), "l"(b), "l"(c));
    return d;
}

__device__ float g_q[131072L * 200];
__device__ float g_k[131072L * 200];
__device__ float g_v[131072L * 200];
__device__ float g_ctx[131072L * 200];

// ------------------------ SGEMM: (M x 200) @ (200 x 200) -------------------
// Full W resident in smem. 80-row A tile, 512 threads = (rg 0..9, cg 0..49),
// micro-tile 8 rows x 4 cols. k-split f32x2: acc lanes hold even/odd-k
// partial sums; x pairs come straight from LDS.64, W pairs packed crosswise.
__global__ __launch_bounds__(512, 1)
void sgemm200(const float* __restrict__ A, const float* __restrict__ B,
              float* __restrict__ C) {
    extern __shared__ float sm[];
    float* ws = sm;                 // 200*200 = 40000 floats
    float* xs = sm + 40000;         // 80 * DPAD floats
    const int tid = threadIdx.x;

    // Load W (10000 float4), coalesced.
    {
        const float4* B4 = (const float4*)B;
        float4* ws4 = (float4*)ws;
        #pragma unroll
        for (int i0 = 0; i0 < 20; i0++) {
            int idx = tid + i0 * 512;
            if (idx < 10000) ws4[idx] = B4[idx];
        }
    }
    // Load A tile (80 x 200) as float2 into pitch-202 smem.
    const long row0 = (long)blockIdx.x * 80;
    long rem = M_ROWS - row0;
    const int rows = rem < 80 ? (int)rem : 80;
    {
        const float2* Ab = (const float2*)(A + row0 * 200);
        for (int i = tid; i < 8000; i += 512) {
            int r = i / 100;
            int c = i - r * 100;
            if (r < rows) *(float2*)(xs + r * DPAD + c * 2) = Ab[i];
        }
    }
    __syncthreads();

    const int cg = tid % 50;
    const int rg = tid / 50;
    if (rg < 10) {
        u64 acc[8][4];
        #pragma unroll
        for (int rr = 0; rr < 8; rr++) {
            acc[rr][0] = 0ull; acc[rr][1] = 0ull;
            acc[rr][2] = 0ull; acc[rr][3] = 0ull;
        }
        const float* xb = xs + rg * 8 * DPAD;
        const float4* wc = (const float4*)ws + cg;   // column-quad of W
        #pragma unroll 2
        for (int k = 0; k < 200; k += 2) {
            float4 wa = wc[k * 50];
            float4 wb = wc[(k + 1) * 50];
            u64 wp0 = pk2(wa.x, wb.x);
            u64 wp1 = pk2(wa.y, wb.y);
            u64 wp2 = pk2(wa.z, wb.z);
            u64 wp3 = pk2(wa.w, wb.w);
            #pragma unroll
            for (int rr = 0; rr < 8; rr++) {
                u64 xp = *(const u64*)(xb + rr * DPAD + k);   // {x[k],x[k+1]}
                acc[rr][0] = ffma2(xp, wp0, acc[rr][0]);
                acc[rr][1] = ffma2(xp, wp1, acc[rr][1]);
                acc[rr][2] = ffma2(xp, wp2, acc[rr][2]);
                acc[rr][3] = ffma2(xp, wp3, acc[rr][3]);
            }
        }
        #pragma unroll
        for (int rr = 0; rr < 8; rr++) {
            int r = rg * 8 + rr;
            if (r < rows) {
                float lo, hi, v0, v1, v2, v3;
                upk2(lo, hi, acc[rr][0]); v0 = lo + hi;
                upk2(lo, hi, acc[rr][1]); v1 = lo + hi;
                upk2(lo, hi, acc[rr][2]); v2 = lo + hi;
                upk2(lo, hi, acc[rr][3]); v3 = lo + hi;
                *(float4*)(C + (row0 + r) * 200 + cg * 4) =
                    make_float4(v0, v1, v2, v3);
            }
        }
    }
}

// --------------------------- Attention per (i, h) --------------------------
// 128 threads, thread = query row. Scores are analytically bounded (|s|<~2),
// so softmax max-subtraction is skipped: ONE fused pass computes QK (scale
// folded into the K tile), exp, running sum, AV accumulation, and stages the
// e-row into smem (pitch 132: STS.128/LDS.128 both bank-conflict-free).
__global__ __launch_bounds__(128, 2)
void attn128(const float* __restrict__ Q, const float* __restrict__ K,
             const float* __restrict__ V, float* __restrict__ AW,
             float* __restrict__ CTX) {
    extern __shared__ float sm[];
    float* ks   = sm;                       // 128*20 (pre-scaled by 1/sqrt(hd))
    float* vs   = sm + 2560;                // 128*20
    float* as   = sm + 5120;                // 128*132 e-values
    float* sinv = sm + 5120 + 128 * 132;    // 128

    const int i   = blockIdx.x;   // 0..1023
    const int h   = blockIdx.y;   // 0..9
    const int tid = threadIdx.x;  // query row
    const long rb = (long)i * 128;
    const int hoff = h * 20;
    const float scale = 0.22360679774997896f;   // 1/sqrt(20)

    // Cooperative load of K,V head slices: 128 rows x 5 float4.
    {
        float4* ks4 = (float4*)ks;
        float4* vs4 = (float4*)vs;
        #pragma unroll
        for (int e0 = 0; e0 < 5; e0++) {
            int e = tid + e0 * 128;
            int r = e / 5, c = e - r * 5;
            const float* kp = K + (rb + r) * 200 + hoff + c * 4;
            const float* vp = V + (rb + r) * 200 + hoff + c * 4;
            float4 k4 = *(const float4*)kp;
            k4.x *= scale; k4.y *= scale; k4.z *= scale; k4.w *= scale;
            ks4[e] = k4;
            vs4[e] = *(const float4*)vp;
        }
    }
    // q row -> 10 packed f32x2 (direct 8B loads; head offset is 8B-aligned).
    u64 qp[10];
    {
        const u64* qg = (const u64*)(Q + (rb + tid) * 200 + hoff);
        #pragma unroll
        for (int j = 0; j < 10; j++) qp[j] = qg[j];
    }
    __syncthreads();

    u64 o2[10];
    #pragma unroll
    for (int j = 0; j < 10; j++) o2[j] = 0ull;
    float ssum = 0.f;
    float ebuf0, ebuf1, ebuf2;
    float* myrow = as + tid * 132;

    #pragma unroll 2
    for (int t = 0; t < 128; t++) {
        const u64* kr = (const u64*)(ks + t * 20);
        u64 a0 = 0ull, a1 = 0ull;
        #pragma unroll
        for (int j = 0; j < 5; j++) {
            a0 = ffma2(qp[2 * j],     kr[2 * j],     a0);
            a1 = ffma2(qp[2 * j + 1], kr[2 * j + 1], a1);
        }
        float l0, h0, l1, h1;
        upk2(l0, h0, a0);
        upk2(l1, h1, a1);
        float s = (l0 + h0) + (l1 + h1);
        float e = __expf(s);
        ssum += e;
        // stage e; STS.128 every 4th t (conflict-free: banks 4*tid+t tile)
        int ph = t & 3;
        if (ph == 0)      ebuf0 = e;
        else if (ph == 1) ebuf1 = e;
        else if (ph == 2) ebuf2 = e;
        else *(float4*)(myrow + (t - 3)) = make_float4(ebuf0, ebuf1, ebuf2, e);
        // AV accumulate
        u64 ee = pk2(e, e);
        const u64* vr = (const u64*)(vs + t * 20);
        #pragma unroll
        for (int j = 0; j < 10; j++) o2[j] = ffma2(ee, vr[j], o2[j]);
    }

    const float inv = 1.0f / ssum;
    sinv[tid] = inv;
    // ctx write (normalization folded in)
    {
        float* cp = CTX + (rb + tid) * 200 + hoff;
        #pragma unroll
        for (int j = 0; j < 5; j++) {
            float l0, h0, l1, h1;
            upk2(l0, h0, o2[2 * j]);
            upk2(l1, h1, o2[2 * j + 1]);
            *(float4*)(cp + j * 4) =
                make_float4(l0 * inv, h0 * inv, l1 * inv, h1 * inv);
        }
    }
    __syncthreads();

    // Coalesced attention-weight store: 4096 float4 per block.
    // Per warp: s is constant, lane = float4 index -> LDS.128 conflict-free.
    {
        float4* awp = (float4*)(AW + (long)(i * 10 + h) * 16384);
        #pragma unroll
        for (int e0 = 0; e0 < 32; e0++) {
            int e = tid + e0 * 128;
            int s  = e >> 5;
            int l  = e & 31;
            float4 v4 = *(const float4*)(as + s * 132 + l * 4);
            float iv = sinv[s];
            awp[e] = make_float4(v4.x * iv, v4.y * iv, v4.z * iv, v4.w * iv);
        }
    }
}

// ---------------------------------------------------------------------------
extern "C" void kernel_launch(void* const* d_in, const int* in_sizes, int n_in,
                              void* d_out, int out_size) {
    const float* x  = (const float*)d_in[0];
    const float* wq = (const float*)d_in[1];
    const float* wk = (const float*)d_in[2];
    const float* wv = (const float*)d_in[3];

    float* attn = (float*)d_out;                       // 1024*10*128*128
    float* out  = (float*)d_out + 167772160L;          // 131072*200

    float *gq, *gk, *gv, *gctx;
    cudaGetSymbolAddress((void**)&gq,   g_q);
    cudaGetSymbolAddress((void**)&gk,   g_k);
    cudaGetSymbolAddress((void**)&gv,   g_v);
    cudaGetSymbolAddress((void**)&gctx, g_ctx);

    const int SG_SMEM = (40000 + 80 * DPAD) * 4;                 // 224640 B
    const int AT_SMEM = (2560 + 2560 + 128 * 132 + 128) * 4;     //  88576 B
    cudaFuncSetAttribute(sgemm200, cudaFuncAttributeMaxDynamicSharedMemorySize, SG_SMEM);
    cudaFuncSetAttribute(attn128,  cudaFuncAttributeMaxDynamicSharedMemorySize, AT_SMEM);

    dim3 gg((131072 + 79) / 80);   // 1639 blocks

    sgemm200<<<gg, 512, SG_SMEM>>>(x, wq, gq);
    sgemm200<<<gg, 512, SG_SMEM>>>(x, wk, gk);
    sgemm200<<<gg, 512, SG_SMEM>>>(x, wv, gv);
    attn128<<<dim3(1024, 10), 128, AT_SMEM>>>(gq, gk, gv, attn, gctx);
    sgemm200<<<gg, 512, SG_SMEM>>>(gctx, wq, out);
}

// round 5
// speedup vs baseline: 2.6692x; 2.6692x over previous
#include <cuda_runtime.h>
#include <cuda_bf16.h>
#include <cstdint>

// ---------------------------------------------------------------------------
// MultiHeadSelfAttention: B=128,H=128,F=8,D=200, nh=10, hd=20
// x flat: (131072, 200). Q/K/V/out projections via mma.sync bf16 3-pass split
// (baseline PTX -> works on plain sm_103 target). attn per (i,h) fp32 (R1).
// ---------------------------------------------------------------------------

typedef unsigned long long u64;

// ---------------- fp32 scratch ----------------
__device__ float g_q[131072L * 200];
__device__ float g_k[131072L * 200];
__device__ float g_v[131072L * 200];
__device__ float g_ctx[131072L * 200];
// ---------------- bf16 split weights (transposed) ----------------
__device__ __nv_bfloat16 g_whi[3][208 * 256];
__device__ __nv_bfloat16 g_wlo[3][208 * 256];

// =========================== helpers =======================================
// pack {lo,hi} floats -> bf16x2 (first PTX operand = upper half)
__device__ __forceinline__ uint32_t pkbf(float lo, float hi) {
    uint32_t r;
    asm("cvt.rn.bf16x2.f32 %0, %1, %2;" : "=r"(r) : "f"(hi), "f"(lo));
    return r;
}
__device__ __forceinline__ float bf_lo(uint32_t p) { return __uint_as_float(p << 16); }
__device__ __forceinline__ float bf_hi(uint32_t p) { return __uint_as_float(p & 0xFFFF0000u); }

__device__ __forceinline__ void mma_bf16(float* d, const uint32_t* a,
                                         uint32_t b0, uint32_t b1) {
    asm volatile(
        "mma.sync.aligned.m16n8k16.row.col.f32.bf16.bf16.f32 "
        "{%0,%1,%2,%3}, {%4,%5,%6,%7}, {%8,%9}, {%0,%1,%2,%3};"
        : "+f"(d[0]), "+f"(d[1]), "+f"(d[2]), "+f"(d[3])
        : "r"(a[0]), "r"(a[1]), "r"(a[2]), "r"(a[3]), "r"(b0), "r"(b1));
}

// =================== W -> Wt[208][256] bf16 hi/lo (transpose+split) ========
__global__ __launch_bounds__(256)
void conv_wt(const float* __restrict__ W, __nv_bfloat16* __restrict__ hi,
             __nv_bfloat16* __restrict__ lo) {
    int idx = blockIdx.x * 256 + threadIdx.x;     // over 208*256
    int n = idx >> 8, k = idx & 255;
    float v = (n < 200 && k < 200) ? W[k * 200 + n] : 0.f;
    __nv_bfloat16 h = __float2bfloat16(v);
    float r = v - __bfloat162float(h);
    hi[idx] = h;
    lo[idx] = __float2bfloat16(r);
}

// ======================= mma.sync bf16-split GEMM ==========================
// C[131072 x 200] = A[131072 x 200](fp32) @ Wt^T, A converted in-kernel.
// Block: 128 rows x 208 cols. 8 warps = 4(M) x 2(N); warp = 32 x 104.
// smem pitch 72 bf16 (144B) -> fragment LDS bank = 4g+t, conflict-free.
#define AH_OFF 0
#define AL_OFF 18432
#define BH_OFF 36864
#define BL_OFF 66816
#define GEMM_SMEM 96768

__device__ __forceinline__ void load_a_chunk(const float* __restrict__ A,
                                             long row0, int tid, int kb,
                                             float4* abuf) {
    int r = tid >> 1, half = tid & 1;
    const float* ap = A + (row0 + r) * 200;
    #pragma unroll
    for (int q = 0; q < 8; q++) {
        int col0 = kb + half * 32 + q * 4;
        abuf[q] = (col0 < 200) ? *(const float4*)(ap + col0)
                               : make_float4(0.f, 0.f, 0.f, 0.f);
    }
}

__global__ __launch_bounds__(256, 1)
void gemm_mma(const float* __restrict__ A,
              const __nv_bfloat16* __restrict__ Bh,
              const __nv_bfloat16* __restrict__ Bl,
              float* __restrict__ C) {
    extern __shared__ char smem[];
    const int tid  = threadIdx.x;
    const int wid  = tid >> 5, lane = tid & 31;
    const int wm   = wid >> 1, wn = wid & 1;
    const int g    = lane >> 2, t = lane & 3;
    const long row0 = (long)blockIdx.x * 128;

    float acc[2][13][4];
    #pragma unroll
    for (int mt = 0; mt < 2; mt++)
        #pragma unroll
        for (int nt = 0; nt < 13; nt++)
            #pragma unroll
            for (int e = 0; e < 4; e++) acc[mt][nt][e] = 0.f;

    float4 abuf[8];
    load_a_chunk(A, row0, tid, 0, abuf);

    const uint32_t* AH32 = (const uint32_t*)(smem + AH_OFF);
    const uint32_t* AL32 = (const uint32_t*)(smem + AL_OFF);
    const uint32_t* BH32 = (const uint32_t*)(smem + BH_OFF);
    const uint32_t* BL32 = (const uint32_t*)(smem + BL_OFF);

    #pragma unroll 1
    for (int c = 0; c < 4; c++) {
        const int kb = c * 64;
        __syncthreads();   // previous chunk's MMA done -> smem reusable

        // ---- convert prefetched A regs -> smem bf16 hi/lo ----
        {
            int r = tid >> 1, half = tid & 1;
            char* ahp = smem + AH_OFF + r * 144 + half * 64;
            char* alp = smem + AL_OFF + r * 144 + half * 64;
            #pragma unroll
            for (int q = 0; q < 8; q++) {
                float4 v = abuf[q];
                uint32_t h01 = pkbf(v.x, v.y);
                uint32_t h23 = pkbf(v.z, v.w);
                float rx = v.x - bf_lo(h01), ry = v.y - bf_hi(h01);
                float rz = v.z - bf_lo(h23), rw = v.w - bf_hi(h23);
                uint32_t l01 = pkbf(rx, ry);
                uint32_t l23 = pkbf(rz, rw);
                *(uint32_t*)(ahp + q * 8)     = h01;
                *(uint32_t*)(ahp + q * 8 + 4) = h23;
                *(uint32_t*)(alp + q * 8)     = l01;
                *(uint32_t*)(alp + q * 8 + 4) = l23;
            }
        }
        // ---- B chunk: gmem bf16 -> smem (pitch 72) ----
        {
            #pragma unroll
            for (int i = 0; i < 13; i++) {
                int e = tid + i * 256;       // 3328 float2 per buffer
                int n = e >> 4, kq = e & 15;
                *(float2*)(smem + BH_OFF + n * 144 + kq * 8) =
                    *(const float2*)(Bh + n * 256 + kb + kq * 4);
                *(float2*)(smem + BL_OFF + n * 144 + kq * 8) =
                    *(const float2*)(Bl + n * 256 + kb + kq * 4);
            }
        }
        // ---- prefetch next A chunk (latency hidden under MMA) ----
        if (c < 3) load_a_chunk(A, row0, tid, kb + 64, abuf);
        __syncthreads();

        const int nst = (c < 3) ? 4 : 1;     // K=208 total
        #pragma unroll 1
        for (int ks = 0; ks < nst; ks++) {
            uint32_t ah[2][4], al[2][4];
            #pragma unroll
            for (int mt = 0; mt < 2; mt++) {
                int r0 = wm * 32 + mt * 16 + g;
                int base = r0 * 36 + ks * 8 + t;
                ah[mt][0] = AH32[base];
                ah[mt][1] = AH32[base + 8 * 36];
                ah[mt][2] = AH32[base + 4];
                ah[mt][3] = AH32[base + 8 * 36 + 4];
                al[mt][0] = AL32[base];
                al[mt][1] = AL32[base + 8 * 36];
                al[mt][2] = AL32[base + 4];
                al[mt][3] = AL32[base + 8 * 36 + 4];
            }
            #pragma unroll
            for (int nt = 0; nt < 13; nt++) {
                int n = wn * 104 + nt * 8 + g;
                int bb = n * 36 + ks * 8 + t;
                uint32_t bh0 = BH32[bb], bh1 = BH32[bb + 4];
                uint32_t bl0 = BL32[bb], bl1 = BL32[bb + 4];
                #pragma unroll
                for (int mt = 0; mt < 2; mt++) {
                    mma_bf16(acc[mt][nt], ah[mt], bh0, bh1);
                    mma_bf16(acc[mt][nt], ah[mt], bl0, bl1);
                    mma_bf16(acc[mt][nt], al[mt], bh0, bh1);
                }
            }
        }
    }

    // ---- epilogue: direct fp32 stores (float2 per row-half) ----
    #pragma unroll
    for (int mt = 0; mt < 2; mt++) {
        long r0 = row0 + wm * 32 + mt * 16 + g;
        #pragma unroll
        for (int nt = 0; nt < 13; nt++) {
            int col = wn * 104 + nt * 8 + t * 2;
            if (col < 200) {
                *(float2*)(C + r0 * 200 + col) =
                    make_float2(acc[mt][nt][0], acc[mt][nt][1]);
                *(float2*)(C + (r0 + 8) * 200 + col) =
                    make_float2(acc[mt][nt][2], acc[mt][nt][3]);
            }
        }
    }
}

// ====================== Attention per (i, h) — R1 version ==================
__global__ __launch_bounds__(128, 2)
void attn128(const float* __restrict__ Q, const float* __restrict__ K,
             const float* __restrict__ V, float* __restrict__ AW,
             float* __restrict__ CTX) {
    extern __shared__ float sm[];
    float* ks   = sm;                       // 128*20
    float* vs   = sm + 2560;                // 128*20
    float* as   = sm + 5120;                // 128*129
    float* sinv = sm + 5120 + 128 * 129;    // 128

    const int i   = blockIdx.x;
    const int h   = blockIdx.y;
    const int tid = threadIdx.x;
    const long rb = (long)i * 128;
    const int hoff = h * 20;

    {
        float4* ks4 = (float4*)ks;
        float4* vs4 = (float4*)vs;
        #pragma unroll
        for (int e0 = 0; e0 < 5; e0++) {
            int e = tid + e0 * 128;
            int r = e / 5, c = e - r * 5;
            const float* kp = K + (rb + r) * 200 + hoff + c * 4;
            const float* vp = V + (rb + r) * 200 + hoff + c * 4;
            ks4[e] = *(const float4*)kp;
            vs4[e] = *(const float4*)vp;
        }
    }
    float q[20];
    {
        const float* qp = Q + (rb + tid) * 200 + hoff;
        #pragma unroll
        for (int c = 0; c < 5; c++) {
            float4 t4 = *(const float4*)(qp + c * 4);
            q[c * 4 + 0] = t4.x; q[c * 4 + 1] = t4.y;
            q[c * 4 + 2] = t4.z; q[c * 4 + 3] = t4.w;
        }
        const float scale = 0.22360679774997896f;
        #pragma unroll
        for (int j = 0; j < 20; j++) q[j] *= scale;
    }
    __syncthreads();

    float* myrow = as + tid * 129;
    float mx = -1e30f;
    #pragma unroll 4
    for (int t = 0; t < 128; t++) {
        const float4* kt = (const float4*)(ks + t * 20);
        float acc = 0.f;
        #pragma unroll
        for (int c = 0; c < 5; c++) {
            float4 k4 = kt[c];
            acc += q[c * 4 + 0] * k4.x + q[c * 4 + 1] * k4.y
                 + q[c * 4 + 2] * k4.z + q[c * 4 + 3] * k4.w;
        }
        myrow[t] = acc;
        mx = fmaxf(mx, acc);
    }
    float ssum = 0.f;
    #pragma unroll 4
    for (int t = 0; t < 128; t++) {
        float e = __expf(myrow[t] - mx);
        myrow[t] = e;
        ssum += e;
    }
    const float inv = 1.0f / ssum;
    sinv[tid] = inv;

    float o[20];
    #pragma unroll
    for (int j = 0; j < 20; j++) o[j] = 0.f;
    #pragma unroll 2
    for (int t = 0; t < 128; t++) {
        float a = myrow[t];
        const float4* vt = (const float4*)(vs + t * 20);
        #pragma unroll
        for (int c = 0; c < 5; c++) {
            float4 v4 = vt[c];
            o[c * 4 + 0] += a * v4.x; o[c * 4 + 1] += a * v4.y;
            o[c * 4 + 2] += a * v4.z; o[c * 4 + 3] += a * v4.w;
        }
    }
    {
        float* cp = CTX + (rb + tid) * 200 + hoff;
        #pragma unroll
        for (int c = 0; c < 5; c++) {
            *(float4*)(cp + c * 4) = make_float4(
                o[c * 4 + 0] * inv, o[c * 4 + 1] * inv,
                o[c * 4 + 2] * inv, o[c * 4 + 3] * inv);
        }
    }
    __syncthreads();

    {
        float4* awp = (float4*)(AW + (long)(i * 10 + h) * 16384);
        #pragma unroll
        for (int e0 = 0; e0 < 32; e0++) {
            int e = tid + e0 * 128;
            int s  = e >> 5;
            int l  = e & 31;
            const float* src = as + s * 129 + l * 4;
            float iv = sinv[s];
            awp[e] = make_float4(src[0] * iv, src[1] * iv, src[2] * iv, src[3] * iv);
        }
    }
}

// ---------------------------------------------------------------------------
extern "C" void kernel_launch(void* const* d_in, const int* in_sizes, int n_in,
                              void* d_out, int out_size) {
    const float* x  = (const float*)d_in[0];
    const float* wq = (const float*)d_in[1];
    const float* wk = (const float*)d_in[2];
    const float* wv = (const float*)d_in[3];

    float* attn = (float*)d_out;                       // 1024*10*128*128
    float* out  = (float*)d_out + 167772160L;          // 131072*200

    float *gq, *gk, *gv, *gctx;
    __nv_bfloat16 *whi, *wlo;
    cudaGetSymbolAddress((void**)&gq,   g_q);
    cudaGetSymbolAddress((void**)&gk,   g_k);
    cudaGetSymbolAddress((void**)&gv,   g_v);
    cudaGetSymbolAddress((void**)&gctx, g_ctx);
    cudaGetSymbolAddress((void**)&whi,  g_whi);
    cudaGetSymbolAddress((void**)&wlo,  g_wlo);

    const int AT_SMEM = (2560 + 2560 + 128 * 129 + 128) * 4;     // 87040 B
    cudaFuncSetAttribute(gemm_mma, cudaFuncAttributeMaxDynamicSharedMemorySize, GEMM_SMEM);
    cudaFuncSetAttribute(attn128,  cudaFuncAttributeMaxDynamicSharedMemorySize, AT_SMEM);

    const int WSZ = 208 * 256;

    conv_wt<<<208, 256>>>(wq, whi + 0 * WSZ, wlo + 0 * WSZ);
    conv_wt<<<208, 256>>>(wk, whi + 1 * WSZ, wlo + 1 * WSZ);
    conv_wt<<<208, 256>>>(wv, whi + 2 * WSZ, wlo + 2 * WSZ);

    gemm_mma<<<1024, 256, GEMM_SMEM>>>(x, whi + 0 * WSZ, wlo + 0 * WSZ, gq);
    gemm_mma<<<1024, 256, GEMM_SMEM>>>(x, whi + 1 * WSZ, wlo + 1 * WSZ, gk);
    gemm_mma<<<1024, 256, GEMM_SMEM>>>(x, whi + 2 * WSZ, wlo + 2 * WSZ, gv);

    attn128<<<dim3(1024, 10), 128, AT_SMEM>>>(gq, gk, gv, attn, gctx);

    gemm_mma<<<1024, 256, GEMM_SMEM>>>(gctx, whi + 0 * WSZ, wlo + 0 * WSZ, out);
}

// round 6
// speedup vs baseline: 2.6703x; 1.0004x over previous
#include <cuda_runtime.h>
#include <cuda_bf16.h>
#include <cstdint>

// ---------------------------------------------------------------------------
// MultiHeadSelfAttention: B=128,H=128,F=8,D=200, nh=10, hd=20
// x flat: (131072, 200). Q/K/V/out projections via mma.sync bf16 3-pass split
// (baseline PTX -> works on plain sm_103 target). attn per (i,h) fp32 (R1).
// ---------------------------------------------------------------------------

typedef unsigned long long u64;

// ---------------- fp32 scratch ----------------
__device__ float g_q[131072L * 200];
__device__ float g_k[131072L * 200];
__device__ float g_v[131072L * 200];
__device__ float g_ctx[131072L * 200];
// ---------------- bf16 split weights (transposed) ----------------
__device__ __nv_bfloat16 g_whi[3][208 * 256];
__device__ __nv_bfloat16 g_wlo[3][208 * 256];

// =========================== helpers =======================================
// pack {lo,hi} floats -> bf16x2 (first PTX operand = upper half)
__device__ __forceinline__ uint32_t pkbf(float lo, float hi) {
    uint32_t r;
    asm("cvt.rn.bf16x2.f32 %0, %1, %2;" : "=r"(r) : "f"(hi), "f"(lo));
    return r;
}
__device__ __forceinline__ float bf_lo(uint32_t p) { return __uint_as_float(p << 16); }
__device__ __forceinline__ float bf_hi(uint32_t p) { return __uint_as_float(p & 0xFFFF0000u); }

__device__ __forceinline__ void mma_bf16(float* d, const uint32_t* a,
                                         uint32_t b0, uint32_t b1) {
    asm volatile(
        "mma.sync.aligned.m16n8k16.row.col.f32.bf16.bf16.f32 "
        "{%0,%1,%2,%3}, {%4,%5,%6,%7}, {%8,%9}, {%0,%1,%2,%3};"
        : "+f"(d[0]), "+f"(d[1]), "+f"(d[2]), "+f"(d[3])
        : "r"(a[0]), "r"(a[1]), "r"(a[2]), "r"(a[3]), "r"(b0), "r"(b1));
}

// =================== W -> Wt[208][256] bf16 hi/lo (transpose+split) ========
__global__ __launch_bounds__(256)
void conv_wt(const float* __restrict__ W, __nv_bfloat16* __restrict__ hi,
             __nv_bfloat16* __restrict__ lo) {
    int idx = blockIdx.x * 256 + threadIdx.x;     // over 208*256
    int n = idx >> 8, k = idx & 255;
    float v = (n < 200 && k < 200) ? W[k * 200 + n] : 0.f;
    __nv_bfloat16 h = __float2bfloat16(v);
    float r = v - __bfloat162float(h);
    hi[idx] = h;
    lo[idx] = __float2bfloat16(r);
}

// ======================= mma.sync bf16-split GEMM ==========================
// C[131072 x 200] = A[131072 x 200](fp32) @ Wt^T, A converted in-kernel.
// Block: 128 rows x 208 cols. 8 warps = 4(M) x 2(N); warp = 32 x 104.
// smem pitch 72 bf16 (144B) -> fragment LDS bank = 4g+t, conflict-free.
#define AH_OFF 0
#define AL_OFF 18432
#define BH_OFF 36864
#define BL_OFF 66816
#define GEMM_SMEM 96768

__device__ __forceinline__ void load_a_chunk(const float* __restrict__ A,
                                             long row0, int tid, int kb,
                                             float4* abuf) {
    int r = tid >> 1, half = tid & 1;
    const float* ap = A + (row0 + r) * 200;
    #pragma unroll
    for (int q = 0; q < 8; q++) {
        int col0 = kb + half * 32 + q * 4;
        abuf[q] = (col0 < 200) ? *(const float4*)(ap + col0)
                               : make_float4(0.f, 0.f, 0.f, 0.f);
    }
}

__global__ __launch_bounds__(256, 1)
void gemm_mma(const float* __restrict__ A,
              const __nv_bfloat16* __restrict__ Bh,
              const __nv_bfloat16* __restrict__ Bl,
              float* __restrict__ C) {
    extern __shared__ char smem[];
    const int tid  = threadIdx.x;
    const int wid  = tid >> 5, lane = tid & 31;
    const int wm   = wid >> 1, wn = wid & 1;
    const int g    = lane >> 2, t = lane & 3;
    const long row0 = (long)blockIdx.x * 128;

    float acc[2][13][4];
    #pragma unroll
    for (int mt = 0; mt < 2; mt++)
        #pragma unroll
        for (int nt = 0; nt < 13; nt++)
            #pragma unroll
            for (int e = 0; e < 4; e++) acc[mt][nt][e] = 0.f;

    float4 abuf[8];
    load_a_chunk(A, row0, tid, 0, abuf);

    const uint32_t* AH32 = (const uint32_t*)(smem + AH_OFF);
    const uint32_t* AL32 = (const uint32_t*)(smem + AL_OFF);
    const uint32_t* BH32 = (const uint32_t*)(smem + BH_OFF);
    const uint32_t* BL32 = (const uint32_t*)(smem + BL_OFF);

    #pragma unroll 1
    for (int c = 0; c < 4; c++) {
        const int kb = c * 64;
        __syncthreads();   // previous chunk's MMA done -> smem reusable

        // ---- convert prefetched A regs -> smem bf16 hi/lo ----
        {
            int r = tid >> 1, half = tid & 1;
            char* ahp = smem + AH_OFF + r * 144 + half * 64;
            char* alp = smem + AL_OFF + r * 144 + half * 64;
            #pragma unroll
            for (int q = 0; q < 8; q++) {
                float4 v = abuf[q];
                uint32_t h01 = pkbf(v.x, v.y);
                uint32_t h23 = pkbf(v.z, v.w);
                float rx = v.x - bf_lo(h01), ry = v.y - bf_hi(h01);
                float rz = v.z - bf_lo(h23), rw = v.w - bf_hi(h23);
                uint32_t l01 = pkbf(rx, ry);
                uint32_t l23 = pkbf(rz, rw);
                *(uint32_t*)(ahp + q * 8)     = h01;
                *(uint32_t*)(ahp + q * 8 + 4) = h23;
                *(uint32_t*)(alp + q * 8)     = l01;
                *(uint32_t*)(alp + q * 8 + 4) = l23;
            }
        }
        // ---- B chunk: gmem bf16 -> smem (pitch 72) ----
        {
            #pragma unroll
            for (int i = 0; i < 13; i++) {
                int e = tid + i * 256;       // 3328 float2 per buffer
                int n = e >> 4, kq = e & 15;
                *(float2*)(smem + BH_OFF + n * 144 + kq * 8) =
                    *(const float2*)(Bh + n * 256 + kb + kq * 4);
                *(float2*)(smem + BL_OFF + n * 144 + kq * 8) =
                    *(const float2*)(Bl + n * 256 + kb + kq * 4);
            }
        }
        // ---- prefetch next A chunk (latency hidden under MMA) ----
        if (c < 3) load_a_chunk(A, row0, tid, kb + 64, abuf);
        __syncthreads();

        const int nst = (c < 3) ? 4 : 1;     // K=208 total
        #pragma unroll 1
        for (int ks = 0; ks < nst; ks++) {
            uint32_t ah[2][4], al[2][4];
            #pragma unroll
            for (int mt = 0; mt < 2; mt++) {
                int r0 = wm * 32 + mt * 16 + g;
                int base = r0 * 36 + ks * 8 + t;
                ah[mt][0] = AH32[base];
                ah[mt][1] = AH32[base + 8 * 36];
                ah[mt][2] = AH32[base + 4];
                ah[mt][3] = AH32[base + 8 * 36 + 4];
                al[mt][0] = AL32[base];
                al[mt][1] = AL32[base + 8 * 36];
                al[mt][2] = AL32[base + 4];
                al[mt][3] = AL32[base + 8 * 36 + 4];
            }
            #pragma unroll
            for (int nt = 0; nt < 13; nt++) {
                int n = wn * 104 + nt * 8 + g;
                int bb = n * 36 + ks * 8 + t;
                uint32_t bh0 = BH32[bb], bh1 = BH32[bb + 4];
                uint32_t bl0 = BL32[bb], bl1 = BL32[bb + 4];
                #pragma unroll
                for (int mt = 0; mt < 2; mt++) {
                    mma_bf16(acc[mt][nt], ah[mt], bh0, bh1);
                    mma_bf16(acc[mt][nt], ah[mt], bl0, bl1);
                    mma_bf16(acc[mt][nt], al[mt], bh0, bh1);
                }
            }
        }
    }

    // ---- epilogue: direct fp32 stores (float2 per row-half) ----
    #pragma unroll
    for (int mt = 0; mt < 2; mt++) {
        long r0 = row0 + wm * 32 + mt * 16 + g;
        #pragma unroll
        for (int nt = 0; nt < 13; nt++) {
            int col = wn * 104 + nt * 8 + t * 2;
            if (col < 200) {
                *(float2*)(C + r0 * 200 + col) =
                    make_float2(acc[mt][nt][0], acc[mt][nt][1]);
                *(float2*)(C + (r0 + 8) * 200 + col) =
                    make_float2(acc[mt][nt][2], acc[mt][nt][3]);
            }
        }
    }
}

// ====================== Attention per (i, h) — R1 version ==================
__global__ __launch_bounds__(128, 2)
void attn128(const float* __restrict__ Q, const float* __restrict__ K,
             const float* __restrict__ V, float* __restrict__ AW,
             float* __restrict__ CTX) {
    extern __shared__ float sm[];
    float* ks   = sm;                       // 128*20
    float* vs   = sm + 2560;                // 128*20
    float* as   = sm + 5120;                // 128*129
    float* sinv = sm + 5120 + 128 * 129;    // 128

    const int i   = blockIdx.x;
    const int h   = blockIdx.y;
    const int tid = threadIdx.x;
    const long rb = (long)i * 128;
    const int hoff = h * 20;

    {
        float4* ks4 = (float4*)ks;
        float4* vs4 = (float4*)vs;
        #pragma unroll
        for (int e0 = 0; e0 < 5; e0++) {
            int e = tid + e0 * 128;
            int r = e / 5, c = e - r * 5;
            const float* kp = K + (rb + r) * 200 + hoff + c * 4;
            const float* vp = V + (rb + r) * 200 + hoff + c * 4;
            ks4[e] = *(const float4*)kp;
            vs4[e] = *(const float4*)vp;
        }
    }
    float q[20];
    {
        const float* qp = Q + (rb + tid) * 200 + hoff;
        #pragma unroll
        for (int c = 0; c < 5; c++) {
            float4 t4 = *(const float4*)(qp + c * 4);
            q[c * 4 + 0] = t4.x; q[c * 4 + 1] = t4.y;
            q[c * 4 + 2] = t4.z; q[c * 4 + 3] = t4.w;
        }
        const float scale = 0.22360679774997896f;
        #pragma unroll
        for (int j = 0; j < 20; j++) q[j] *= scale;
    }
    __syncthreads();

    float* myrow = as + tid * 129;
    float mx = -1e30f;
    #pragma unroll 4
    for (int t = 0; t < 128; t++) {
        const float4* kt = (const float4*)(ks + t * 20);
        float acc = 0.f;
        #pragma unroll
        for (int c = 0; c < 5; c++) {
            float4 k4 = kt[c];
            acc += q[c * 4 + 0] * k4.x + q[c * 4 + 1] * k4.y
                 + q[c * 4 + 2] * k4.z + q[c * 4 + 3] * k4.w;
        }
        myrow[t] = acc;
        mx = fmaxf(mx, acc);
    }
    float ssum = 0.f;
    #pragma unroll 4
    for (int t = 0; t < 128; t++) {
        float e = __expf(myrow[t] - mx);
        myrow[t] = e;
        ssum += e;
    }
    const float inv = 1.0f / ssum;
    sinv[tid] = inv;

    float o[20];
    #pragma unroll
    for (int j = 0; j < 20; j++) o[j] = 0.f;
    #pragma unroll 2
    for (int t = 0; t < 128; t++) {
        float a = myrow[t];
        const float4* vt = (const float4*)(vs + t * 20);
        #pragma unroll
        for (int c = 0; c < 5; c++) {
            float4 v4 = vt[c];
            o[c * 4 + 0] += a * v4.x; o[c * 4 + 1] += a * v4.y;
            o[c * 4 + 2] += a * v4.z; o[c * 4 + 3] += a * v4.w;
        }
    }
    {
        float* cp = CTX + (rb + tid) * 200 + hoff;
        #pragma unroll
        for (int c = 0; c < 5; c++) {
            *(float4*)(cp + c * 4) = make_float4(
                o[c * 4 + 0] * inv, o[c * 4 + 1] * inv,
                o[c * 4 + 2] * inv, o[c * 4 + 3] * inv);
        }
    }
    __syncthreads();

    {
        float4* awp = (float4*)(AW + (long)(i * 10 + h) * 16384);
        #pragma unroll
        for (int e0 = 0; e0 < 32; e0++) {
            int e = tid + e0 * 128;
            int s  = e >> 5;
            int l  = e & 31;
            const float* src = as + s * 129 + l * 4;
            float iv = sinv[s];
            awp[e] = make_float4(src[0] * iv, src[1] * iv, src[2] * iv, src[3] * iv);
        }
    }
}

// ---------------------------------------------------------------------------
extern "C" void kernel_launch(void* const* d_in, const int* in_sizes, int n_in,
                              void* d_out, int out_size) {
    const float* x  = (const float*)d_in[0];
    const float* wq = (const float*)d_in[1];
    const float* wk = (const float*)d_in[2];
    const float* wv = (const float*)d_in[3];

    float* attn = (float*)d_out;                       // 1024*10*128*128
    float* out  = (float*)d_out + 167772160L;          // 131072*200

    float *gq, *gk, *gv, *gctx;
    __nv_bfloat16 *whi, *wlo;
    cudaGetSymbolAddress((void**)&gq,   g_q);
    cudaGetSymbolAddress((void**)&gk,   g_k);
    cudaGetSymbolAddress((void**)&gv,   g_v);
    cudaGetSymbolAddress((void**)&gctx, g_ctx);
    cudaGetSymbolAddress((void**)&whi,  g_whi);
    cudaGetSymbolAddress((void**)&wlo,  g_wlo);

    const int AT_SMEM = (2560 + 2560 + 128 * 129 + 128) * 4;     // 87040 B
    cudaFuncSetAttribute(gemm_mma, cudaFuncAttributeMaxDynamicSharedMemorySize, GEMM_SMEM);
    cudaFuncSetAttribute(attn128,  cudaFuncAttributeMaxDynamicSharedMemorySize, AT_SMEM);

    const int WSZ = 208 * 256;

    conv_wt<<<208, 256>>>(wq, whi + 0 * WSZ, wlo + 0 * WSZ);
    conv_wt<<<208, 256>>>(wk, whi + 1 * WSZ, wlo + 1 * WSZ);
    conv_wt<<<208, 256>>>(wv, whi + 2 * WSZ, wlo + 2 * WSZ);

    gemm_mma<<<1024, 256, GEMM_SMEM>>>(x, whi + 0 * WSZ, wlo + 0 * WSZ, gq);
    gemm_mma<<<1024, 256, GEMM_SMEM>>>(x, whi + 1 * WSZ, wlo + 1 * WSZ, gk);
    gemm_mma<<<1024, 256, GEMM_SMEM>>>(x, whi + 2 * WSZ, wlo + 2 * WSZ, gv);

    attn128<<<dim3(1024, 10), 128, AT_SMEM>>>(gq, gk, gv, attn, gctx);

    gemm_mma<<<1024, 256, GEMM_SMEM>>>(gctx, whi + 0 * WSZ, wlo + 0 * WSZ, out);
}

// round 7
// speedup vs baseline: 2.6709x; 1.0003x over previous
#include <cuda_runtime.h>
#include <cuda_bf16.h>
#include <cstdint>

// ---------------------------------------------------------------------------
// MultiHeadSelfAttention: B=128,H=128,F=8,D=200, nh=10, hd=20
// x flat: (131072, 200). Q/K/V/out projections via mma.sync bf16 3-pass split
// (baseline PTX -> works on plain sm_103 target). attn per (i,h) fp32 (R1).
// ---------------------------------------------------------------------------

typedef unsigned long long u64;

// ---------------- fp32 scratch ----------------
__device__ float g_q[131072L * 200];
__device__ float g_k[131072L * 200];
__device__ float g_v[131072L * 200];
__device__ float g_ctx[131072L * 200];
// ---------------- bf16 split weights (transposed) ----------------
__device__ __nv_bfloat16 g_whi[3][208 * 256];
__device__ __nv_bfloat16 g_wlo[3][208 * 256];

// =========================== helpers =======================================
// pack {lo,hi} floats -> bf16x2 (first PTX operand = upper half)
__device__ __forceinline__ uint32_t pkbf(float lo, float hi) {
    uint32_t r;
    asm("cvt.rn.bf16x2.f32 %0, %1, %2;" : "=r"(r) : "f"(hi), "f"(lo));
    return r;
}
__device__ __forceinline__ float bf_lo(uint32_t p) { return __uint_as_float(p << 16); }
__device__ __forceinline__ float bf_hi(uint32_t p) { return __uint_as_float(p & 0xFFFF0000u); }

__device__ __forceinline__ void mma_bf16(float* d, const uint32_t* a,
                                         uint32_t b0, uint32_t b1) {
    asm volatile(
        "mma.sync.aligned.m16n8k16.row.col.f32.bf16.bf16.f32 "
        "{%0,%1,%2,%3}, {%4,%5,%6,%7}, {%8,%9}, {%0,%1,%2,%3};"
        : "+f"(d[0]), "+f"(d[1]), "+f"(d[2]), "+f"(d[3])
        : "r"(a[0]), "r"(a[1]), "r"(a[2]), "r"(a[3]), "r"(b0), "r"(b1));
}

// =================== W -> Wt[208][256] bf16 hi/lo (transpose+split) ========
__global__ __launch_bounds__(256)
void conv_wt(const float* __restrict__ W, __nv_bfloat16* __restrict__ hi,
             __nv_bfloat16* __restrict__ lo) {
    int idx = blockIdx.x * 256 + threadIdx.x;     // over 208*256
    int n = idx >> 8, k = idx & 255;
    float v = (n < 200 && k < 200) ? W[k * 200 + n] : 0.f;
    __nv_bfloat16 h = __float2bfloat16(v);
    float r = v - __bfloat162float(h);
    hi[idx] = h;
    lo[idx] = __float2bfloat16(r);
}

// ======================= mma.sync bf16-split GEMM ==========================
// C[131072 x 200] = A[131072 x 200](fp32) @ Wt^T, A converted in-kernel.
// Block: 128 rows x 208 cols. 8 warps = 4(M) x 2(N); warp = 32 x 104.
// smem pitch 72 bf16 (144B) -> fragment LDS bank = 4g+t, conflict-free.
#define AH_OFF 0
#define AL_OFF 18432
#define BH_OFF 36864
#define BL_OFF 66816
#define GEMM_SMEM 96768

__device__ __forceinline__ void load_a_chunk(const float* __restrict__ A,
                                             long row0, int tid, int kb,
                                             float4* abuf) {
    int r = tid >> 1, half = tid & 1;
    const float* ap = A + (row0 + r) * 200;
    #pragma unroll
    for (int q = 0; q < 8; q++) {
        int col0 = kb + half * 32 + q * 4;
        abuf[q] = (col0 < 200) ? *(const float4*)(ap + col0)
                               : make_float4(0.f, 0.f, 0.f, 0.f);
    }
}

__global__ __launch_bounds__(256, 1)
void gemm_mma(const float* __restrict__ A,
              const __nv_bfloat16* __restrict__ Bh,
              const __nv_bfloat16* __restrict__ Bl,
              float* __restrict__ C) {
    extern __shared__ char smem[];
    const int tid  = threadIdx.x;
    const int wid  = tid >> 5, lane = tid & 31;
    const int wm   = wid >> 1, wn = wid & 1;
    const int g    = lane >> 2, t = lane & 3;
    const long row0 = (long)blockIdx.x * 128;

    float acc[2][13][4];
    #pragma unroll
    for (int mt = 0; mt < 2; mt++)
        #pragma unroll
        for (int nt = 0; nt < 13; nt++)
            #pragma unroll
            for (int e = 0; e < 4; e++) acc[mt][nt][e] = 0.f;

    float4 abuf[8];
    load_a_chunk(A, row0, tid, 0, abuf);

    const uint32_t* AH32 = (const uint32_t*)(smem + AH_OFF);
    const uint32_t* AL32 = (const uint32_t*)(smem + AL_OFF);
    const uint32_t* BH32 = (const uint32_t*)(smem + BH_OFF);
    const uint32_t* BL32 = (const uint32_t*)(smem + BL_OFF);

    #pragma unroll 1
    for (int c = 0; c < 4; c++) {
        const int kb = c * 64;
        __syncthreads();   // previous chunk's MMA done -> smem reusable

        // ---- convert prefetched A regs -> smem bf16 hi/lo ----
        {
            int r = tid >> 1, half = tid & 1;
            char* ahp = smem + AH_OFF + r * 144 + half * 64;
            char* alp = smem + AL_OFF + r * 144 + half * 64;
            #pragma unroll
            for (int q = 0; q < 8; q++) {
                float4 v = abuf[q];
                uint32_t h01 = pkbf(v.x, v.y);
                uint32_t h23 = pkbf(v.z, v.w);
                float rx = v.x - bf_lo(h01), ry = v.y - bf_hi(h01);
                float rz = v.z - bf_lo(h23), rw = v.w - bf_hi(h23);
                uint32_t l01 = pkbf(rx, ry);
                uint32_t l23 = pkbf(rz, rw);
                *(uint32_t*)(ahp + q * 8)     = h01;
                *(uint32_t*)(ahp + q * 8 + 4) = h23;
                *(uint32_t*)(alp + q * 8)     = l01;
                *(uint32_t*)(alp + q * 8 + 4) = l23;
            }
        }
        // ---- B chunk: gmem bf16 -> smem (pitch 72) ----
        {
            #pragma unroll
            for (int i = 0; i < 13; i++) {
                int e = tid + i * 256;       // 3328 float2 per buffer
                int n = e >> 4, kq = e & 15;
                *(float2*)(smem + BH_OFF + n * 144 + kq * 8) =
                    *(const float2*)(Bh + n * 256 + kb + kq * 4);
                *(float2*)(smem + BL_OFF + n * 144 + kq * 8) =
                    *(const float2*)(Bl + n * 256 + kb + kq * 4);
            }
        }
        // ---- prefetch next A chunk (latency hidden under MMA) ----
        if (c < 3) load_a_chunk(A, row0, tid, kb + 64, abuf);
        __syncthreads();

        const int nst = (c < 3) ? 4 : 1;     // K=208 total
        #pragma unroll 1
        for (int ks = 0; ks < nst; ks++) {
            uint32_t ah[2][4], al[2][4];
            #pragma unroll
            for (int mt = 0; mt < 2; mt++) {
                int r0 = wm * 32 + mt * 16 + g;
                int base = r0 * 36 + ks * 8 + t;
                ah[mt][0] = AH32[base];
                ah[mt][1] = AH32[base + 8 * 36];
                ah[mt][2] = AH32[base + 4];
                ah[mt][3] = AH32[base + 8 * 36 + 4];
                al[mt][0] = AL32[base];
                al[mt][1] = AL32[base + 8 * 36];
                al[mt][2] = AL32[base + 4];
                al[mt][3] = AL32[base + 8 * 36 + 4];
            }
            #pragma unroll
            for (int nt = 0; nt < 13; nt++) {
                int n = wn * 104 + nt * 8 + g;
                int bb = n * 36 + ks * 8 + t;
                uint32_t bh0 = BH32[bb], bh1 = BH32[bb + 4];
                uint32_t bl0 = BL32[bb], bl1 = BL32[bb + 4];
                #pragma unroll
                for (int mt = 0; mt < 2; mt++) {
                    mma_bf16(acc[mt][nt], ah[mt], bh0, bh1);
                    mma_bf16(acc[mt][nt], ah[mt], bl0, bl1);
                    mma_bf16(acc[mt][nt], al[mt], bh0, bh1);
                }
            }
        }
    }

    // ---- epilogue: direct fp32 stores (float2 per row-half) ----
    #pragma unroll
    for (int mt = 0; mt < 2; mt++) {
        long r0 = row0 + wm * 32 + mt * 16 + g;
        #pragma unroll
        for (int nt = 0; nt < 13; nt++) {
            int col = wn * 104 + nt * 8 + t * 2;
            if (col < 200) {
                *(float2*)(C + r0 * 200 + col) =
                    make_float2(acc[mt][nt][0], acc[mt][nt][1]);
                *(float2*)(C + (r0 + 8) * 200 + col) =
                    make_float2(acc[mt][nt][2], acc[mt][nt][3]);
            }
        }
    }
}

// ====================== Attention per (i, h) — R1 version ==================
__global__ __launch_bounds__(128, 2)
void attn128(const float* __restrict__ Q, const float* __restrict__ K,
             const float* __restrict__ V, float* __restrict__ AW,
             float* __restrict__ CTX) {
    extern __shared__ float sm[];
    float* ks   = sm;                       // 128*20
    float* vs   = sm + 2560;                // 128*20
    float* as   = sm + 5120;                // 128*129
    float* sinv = sm + 5120 + 128 * 129;    // 128

    const int i   = blockIdx.x;
    const int h   = blockIdx.y;
    const int tid = threadIdx.x;
    const long rb = (long)i * 128;
    const int hoff = h * 20;

    {
        float4* ks4 = (float4*)ks;
        float4* vs4 = (float4*)vs;
        #pragma unroll
        for (int e0 = 0; e0 < 5; e0++) {
            int e = tid + e0 * 128;
            int r = e / 5, c = e - r * 5;
            const float* kp = K + (rb + r) * 200 + hoff + c * 4;
            const float* vp = V + (rb + r) * 200 + hoff + c * 4;
            ks4[e] = *(const float4*)kp;
            vs4[e] = *(const float4*)vp;
        }
    }
    float q[20];
    {
        const float* qp = Q + (rb + tid) * 200 + hoff;
        #pragma unroll
        for (int c = 0; c < 5; c++) {
            float4 t4 = *(const float4*)(qp + c * 4);
            q[c * 4 + 0] = t4.x; q[c * 4 + 1] = t4.y;
            q[c * 4 + 2] = t4.z; q[c * 4 + 3] = t4.w;
        }
        const float scale = 0.22360679774997896f;
        #pragma unroll
        for (int j = 0; j < 20; j++) q[j] *= scale;
    }
    __syncthreads();

    float* myrow = as + tid * 129;
    float mx = -1e30f;
    #pragma unroll 4
    for (int t = 0; t < 128; t++) {
        const float4* kt = (const float4*)(ks + t * 20);
        float acc = 0.f;
        #pragma unroll
        for (int c = 0; c < 5; c++) {
            float4 k4 = kt[c];
            acc += q[c * 4 + 0] * k4.x + q[c * 4 + 1] * k4.y
                 + q[c * 4 + 2] * k4.z + q[c * 4 + 3] * k4.w;
        }
        myrow[t] = acc;
        mx = fmaxf(mx, acc);
    }
    float ssum = 0.f;
    #pragma unroll 4
    for (int t = 0; t < 128; t++) {
        float e = __expf(myrow[t] - mx);
        myrow[t] = e;
        ssum += e;
    }
    const float inv = 1.0f / ssum;
    sinv[tid] = inv;

    float o[20];
    #pragma unroll
    for (int j = 0; j < 20; j++) o[j] = 0.f;
    #pragma unroll 2
    for (int t = 0; t < 128; t++) {
        float a = myrow[t];
        const float4* vt = (const float4*)(vs + t * 20);
        #pragma unroll
        for (int c = 0; c < 5; c++) {
            float4 v4 = vt[c];
            o[c * 4 + 0] += a * v4.x; o[c * 4 + 1] += a * v4.y;
            o[c * 4 + 2] += a * v4.z; o[c * 4 + 3] += a * v4.w;
        }
    }
    {
        float* cp = CTX + (rb + tid) * 200 + hoff;
        #pragma unroll
        for (int c = 0; c < 5; c++) {
            *(float4*)(cp + c * 4) = make_float4(
                o[c * 4 + 0] * inv, o[c * 4 + 1] * inv,
                o[c * 4 + 2] * inv, o[c * 4 + 3] * inv);
        }
    }
    __syncthreads();

    {
        float4* awp = (float4*)(AW + (long)(i * 10 + h) * 16384);
        #pragma unroll
        for (int e0 = 0; e0 < 32; e0++) {
            int e = tid + e0 * 128;
            int s  = e >> 5;
            int l  = e & 31;
            const float* src = as + s * 129 + l * 4;
            float iv = sinv[s];
            awp[e] = make_float4(src[0] * iv, src[1] * iv, src[2] * iv, src[3] * iv);
        }
    }
}

// ---------------------------------------------------------------------------
extern "C" void kernel_launch(void* const* d_in, const int* in_sizes, int n_in,
                              void* d_out, int out_size) {
    const float* x  = (const float*)d_in[0];
    const float* wq = (const float*)d_in[1];
    const float* wk = (const float*)d_in[2];
    const float* wv = (const float*)d_in[3];

    float* attn = (float*)d_out;                       // 1024*10*128*128
    float* out  = (float*)d_out + 167772160L;          // 131072*200

    float *gq, *gk, *gv, *gctx;
    __nv_bfloat16 *whi, *wlo;
    cudaGetSymbolAddress((void**)&gq,   g_q);
    cudaGetSymbolAddress((void**)&gk,   g_k);
    cudaGetSymbolAddress((void**)&gv,   g_v);
    cudaGetSymbolAddress((void**)&gctx, g_ctx);
    cudaGetSymbolAddress((void**)&whi,  g_whi);
    cudaGetSymbolAddress((void**)&wlo,  g_wlo);

    const int AT_SMEM = (2560 + 2560 + 128 * 129 + 128) * 4;     // 87040 B
    cudaFuncSetAttribute(gemm_mma, cudaFuncAttributeMaxDynamicSharedMemorySize, GEMM_SMEM);
    cudaFuncSetAttribute(attn128,  cudaFuncAttributeMaxDynamicSharedMemorySize, AT_SMEM);

    const int WSZ = 208 * 256;

    conv_wt<<<208, 256>>>(wq, whi + 0 * WSZ, wlo + 0 * WSZ);
    conv_wt<<<208, 256>>>(wk, whi + 1 * WSZ, wlo + 1 * WSZ);
    conv_wt<<<208, 256>>>(wv, whi + 2 * WSZ, wlo + 2 * WSZ);

    gemm_mma<<<1024, 256, GEMM_SMEM>>>(x, whi + 0 * WSZ, wlo + 0 * WSZ, gq);
    gemm_mma<<<1024, 256, GEMM_SMEM>>>(x, whi + 1 * WSZ, wlo + 1 * WSZ, gk);
    gemm_mma<<<1024, 256, GEMM_SMEM>>>(x, whi + 2 * WSZ, wlo + 2 * WSZ, gv);

    attn128<<<dim3(1024, 10), 128, AT_SMEM>>>(gq, gk, gv, attn, gctx);

    gemm_mma<<<1024, 256, GEMM_SMEM>>>(gctx, whi + 0 * WSZ, wlo + 0 * WSZ, out);
}

// round 8
// speedup vs baseline: 3.0141x; 1.1285x over previous
#include <cuda_runtime.h>
#include <cuda_bf16.h>
#include <cstdint>

// ---------------------------------------------------------------------------
// MultiHeadSelfAttention: B=128,H=128,F=8,D=200, nh=10, hd=20
// x flat: (131072, 200). Q/K/V/out projections via mma.sync bf16 3-pass split.
// attn per (i,h): 256-thread split-K fp32 kernel (thread = query x key-half).
// ---------------------------------------------------------------------------

typedef unsigned long long u64;

// ---------------- fp32 scratch ----------------
__device__ float g_q[131072L * 200];
__device__ float g_k[131072L * 200];
__device__ float g_v[131072L * 200];
__device__ float g_ctx[131072L * 200];
// ---------------- bf16 split weights (transposed) ----------------
__device__ __nv_bfloat16 g_whi[3][208 * 256];
__device__ __nv_bfloat16 g_wlo[3][208 * 256];

// =========================== helpers =======================================
__device__ __forceinline__ uint32_t pkbf(float lo, float hi) {
    uint32_t r;
    asm("cvt.rn.bf16x2.f32 %0, %1, %2;" : "=r"(r) : "f"(hi), "f"(lo));
    return r;
}
__device__ __forceinline__ float bf_lo(uint32_t p) { return __uint_as_float(p << 16); }
__device__ __forceinline__ float bf_hi(uint32_t p) { return __uint_as_float(p & 0xFFFF0000u); }

__device__ __forceinline__ void mma_bf16(float* d, const uint32_t* a,
                                         uint32_t b0, uint32_t b1) {
    asm volatile(
        "mma.sync.aligned.m16n8k16.row.col.f32.bf16.bf16.f32 "
        "{%0,%1,%2,%3}, {%4,%5,%6,%7}, {%8,%9}, {%0,%1,%2,%3};"
        : "+f"(d[0]), "+f"(d[1]), "+f"(d[2]), "+f"(d[3])
        : "r"(a[0]), "r"(a[1]), "r"(a[2]), "r"(a[3]), "r"(b0), "r"(b1));
}

// =================== W -> Wt[208][256] bf16 hi/lo (transpose+split) ========
__global__ __launch_bounds__(256)
void conv_wt(const float* __restrict__ W, __nv_bfloat16* __restrict__ hi,
             __nv_bfloat16* __restrict__ lo) {
    int idx = blockIdx.x * 256 + threadIdx.x;     // over 208*256
    int n = idx >> 8, k = idx & 255;
    float v = (n < 200 && k < 200) ? W[k * 200 + n] : 0.f;
    __nv_bfloat16 h = __float2bfloat16(v);
    float r = v - __bfloat162float(h);
    hi[idx] = h;
    lo[idx] = __float2bfloat16(r);
}

// ======================= mma.sync bf16-split GEMM (R7, unchanged) ==========
#define AH_OFF 0
#define AL_OFF 18432
#define BH_OFF 36864
#define BL_OFF 66816
#define GEMM_SMEM 96768

__device__ __forceinline__ void load_a_chunk(const float* __restrict__ A,
                                             long row0, int tid, int kb,
                                             float4* abuf) {
    int r = tid >> 1, half = tid & 1;
    const float* ap = A + (row0 + r) * 200;
    #pragma unroll
    for (int q = 0; q < 8; q++) {
        int col0 = kb + half * 32 + q * 4;
        abuf[q] = (col0 < 200) ? *(const float4*)(ap + col0)
                               : make_float4(0.f, 0.f, 0.f, 0.f);
    }
}

__global__ __launch_bounds__(256, 1)
void gemm_mma(const float* __restrict__ A,
              const __nv_bfloat16* __restrict__ Bh,
              const __nv_bfloat16* __restrict__ Bl,
              float* __restrict__ C) {
    extern __shared__ char smem[];
    const int tid  = threadIdx.x;
    const int wid  = tid >> 5, lane = tid & 31;
    const int wm   = wid >> 1, wn = wid & 1;
    const int g    = lane >> 2, t = lane & 3;
    const long row0 = (long)blockIdx.x * 128;

    float acc[2][13][4];
    #pragma unroll
    for (int mt = 0; mt < 2; mt++)
        #pragma unroll
        for (int nt = 0; nt < 13; nt++)
            #pragma unroll
            for (int e = 0; e < 4; e++) acc[mt][nt][e] = 0.f;

    float4 abuf[8];
    load_a_chunk(A, row0, tid, 0, abuf);

    const uint32_t* AH32 = (const uint32_t*)(smem + AH_OFF);
    const uint32_t* AL32 = (const uint32_t*)(smem + AL_OFF);
    const uint32_t* BH32 = (const uint32_t*)(smem + BH_OFF);
    const uint32_t* BL32 = (const uint32_t*)(smem + BL_OFF);

    #pragma unroll 1
    for (int c = 0; c < 4; c++) {
        const int kb = c * 64;
        __syncthreads();

        {
            int r = tid >> 1, half = tid & 1;
            char* ahp = smem + AH_OFF + r * 144 + half * 64;
            char* alp = smem + AL_OFF + r * 144 + half * 64;
            #pragma unroll
            for (int q = 0; q < 8; q++) {
                float4 v = abuf[q];
                uint32_t h01 = pkbf(v.x, v.y);
                uint32_t h23 = pkbf(v.z, v.w);
                float rx = v.x - bf_lo(h01), ry = v.y - bf_hi(h01);
                float rz = v.z - bf_lo(h23), rw = v.w - bf_hi(h23);
                uint32_t l01 = pkbf(rx, ry);
                uint32_t l23 = pkbf(rz, rw);
                *(uint32_t*)(ahp + q * 8)     = h01;
                *(uint32_t*)(ahp + q * 8 + 4) = h23;
                *(uint32_t*)(alp + q * 8)     = l01;
                *(uint32_t*)(alp + q * 8 + 4) = l23;
            }
        }
        {
            #pragma unroll
            for (int i = 0; i < 13; i++) {
                int e = tid + i * 256;
                int n = e >> 4, kq = e & 15;
                *(float2*)(smem + BH_OFF + n * 144 + kq * 8) =
                    *(const float2*)(Bh + n * 256 + kb + kq * 4);
                *(float2*)(smem + BL_OFF + n * 144 + kq * 8) =
                    *(const float2*)(Bl + n * 256 + kb + kq * 4);
            }
        }
        if (c < 3) load_a_chunk(A, row0, tid, kb + 64, abuf);
        __syncthreads();

        const int nst = (c < 3) ? 4 : 1;
        #pragma unroll 1
        for (int ks = 0; ks < nst; ks++) {
            uint32_t ah[2][4], al[2][4];
            #pragma unroll
            for (int mt = 0; mt < 2; mt++) {
                int r0 = wm * 32 + mt * 16 + g;
                int base = r0 * 36 + ks * 8 + t;
                ah[mt][0] = AH32[base];
                ah[mt][1] = AH32[base + 8 * 36];
                ah[mt][2] = AH32[base + 4];
                ah[mt][3] = AH32[base + 8 * 36 + 4];
                al[mt][0] = AL32[base];
                al[mt][1] = AL32[base + 8 * 36];
                al[mt][2] = AL32[base + 4];
                al[mt][3] = AL32[base + 8 * 36 + 4];
            }
            #pragma unroll
            for (int nt = 0; nt < 13; nt++) {
                int n = wn * 104 + nt * 8 + g;
                int bb = n * 36 + ks * 8 + t;
                uint32_t bh0 = BH32[bb], bh1 = BH32[bb + 4];
                uint32_t bl0 = BL32[bb], bl1 = BL32[bb + 4];
                #pragma unroll
                for (int mt = 0; mt < 2; mt++) {
                    mma_bf16(acc[mt][nt], ah[mt], bh0, bh1);
                    mma_bf16(acc[mt][nt], ah[mt], bl0, bl1);
                    mma_bf16(acc[mt][nt], al[mt], bh0, bh1);
                }
            }
        }
    }

    #pragma unroll
    for (int mt = 0; mt < 2; mt++) {
        long r0 = row0 + wm * 32 + mt * 16 + g;
        #pragma unroll
        for (int nt = 0; nt < 13; nt++) {
            int col = wn * 104 + nt * 8 + t * 2;
            if (col < 200) {
                *(float2*)(C + r0 * 200 + col) =
                    make_float2(acc[mt][nt][0], acc[mt][nt][1]);
                *(float2*)(C + (r0 + 8) * 200 + col) =
                    make_float2(acc[mt][nt][2], acc[mt][nt][3]);
            }
        }
    }
}

// ================= Attention per (i, h): 256-thread split-K =================
// thread = (q = tid&127, half = tid>>7); each handles 64 keys.
// Scores bounded -> exp without max-subtraction (validated R2).
// e staged at pitch 132 via STS.128 (conflict-free), AW pass via LDS.128
// (conflict-free: 16B banks tile exactly).
__global__ __launch_bounds__(256, 2)
void attn256(const float* __restrict__ Q, const float* __restrict__ K,
             const float* __restrict__ V, float* __restrict__ AW,
             float* __restrict__ CTX) {
    extern __shared__ float sm[];
    float* ks   = sm;                        // 128*20 (scale folded in)
    float* vs   = sm + 2560;                 // 128*20
    float* es   = sm + 5120;                 // 128*132
    float* sinv = sm + 5120 + 128 * 132;     // 128
    float* sp   = sinv + 128;                // 128 partial sums (half=1)
    float* op   = sp + 128;                  // 128*20 partial AV (half=1)

    const int i    = blockIdx.x;
    const int h    = blockIdx.y;
    const int tid  = threadIdx.x;
    const int q    = tid & 127;
    const int half = tid >> 7;
    const long rb  = (long)i * 128;
    const int hoff = h * 20;
    const float scale = 0.22360679774997896f;   // 1/sqrt(20)

    // K (pre-scaled) and V head slices: 640 float4 each, 256 threads.
    {
        float4* ks4 = (float4*)ks;
        float4* vs4 = (float4*)vs;
        #pragma unroll
        for (int e0 = 0; e0 < 3; e0++) {
            int e = tid + e0 * 256;
            if (e < 640) {
                int r = e / 5, c = e - r * 5;
                float4 k4 = *(const float4*)(K + (rb + r) * 200 + hoff + c * 4);
                k4.x *= scale; k4.y *= scale; k4.z *= scale; k4.w *= scale;
                ks4[e] = k4;
                vs4[e] = *(const float4*)(V + (rb + r) * 200 + hoff + c * 4);
            }
        }
    }
    // q row -> registers (both halves load the same row; L1 broadcast).
    float qr[20];
    {
        const float* qp = Q + (rb + q) * 200 + hoff;
        #pragma unroll
        for (int c = 0; c < 5; c++) {
            float4 t4 = *(const float4*)(qp + c * 4);
            qr[c * 4 + 0] = t4.x; qr[c * 4 + 1] = t4.y;
            qr[c * 4 + 2] = t4.z; qr[c * 4 + 3] = t4.w;
        }
    }
    __syncthreads();

    const int t0 = half * 64;
    float o[20];
    #pragma unroll
    for (int j = 0; j < 20; j++) o[j] = 0.f;
    float ssum = 0.f;
    float eb0, eb1, eb2;
    float* myrow = es + q * 132;

    #pragma unroll 2
    for (int tt = 0; tt < 64; tt++) {
        const int t = t0 + tt;
        const float4* kt = (const float4*)(ks + t * 20);   // warp broadcast
        float acc = 0.f;
        #pragma unroll
        for (int c = 0; c < 5; c++) {
            float4 k4 = kt[c];
            acc += qr[c * 4 + 0] * k4.x + qr[c * 4 + 1] * k4.y
                 + qr[c * 4 + 2] * k4.z + qr[c * 4 + 3] * k4.w;
        }
        float e = __expf(acc);
        ssum += e;
        int ph = tt & 3;
        if (ph == 0)      eb0 = e;
        else if (ph == 1) eb1 = e;
        else if (ph == 2) eb2 = e;
        else *(float4*)(myrow + (t - 3)) = make_float4(eb0, eb1, eb2, e);
        const float4* vt = (const float4*)(vs + t * 20);   // warp broadcast
        #pragma unroll
        for (int c = 0; c < 5; c++) {
            float4 v4 = vt[c];
            o[c * 4 + 0] += e * v4.x; o[c * 4 + 1] += e * v4.y;
            o[c * 4 + 2] += e * v4.z; o[c * 4 + 3] += e * v4.w;
        }
    }

    // combine halves
    if (half == 1) {
        sp[q] = ssum;
        float* od = op + q * 20;
        #pragma unroll
        for (int c = 0; c < 5; c++)
            *(float4*)(od + c * 4) = make_float4(o[c * 4 + 0], o[c * 4 + 1],
                                                 o[c * 4 + 2], o[c * 4 + 3]);
    }
    __syncthreads();
    if (half == 0) {
        const float inv = 1.0f / (ssum + sp[q]);
        sinv[q] = inv;
        const float* od = op + q * 20;
        float* cp = CTX + (rb + q) * 200 + hoff;
        #pragma unroll
        for (int c = 0; c < 5; c++) {
            float4 p4 = *(const float4*)(od + c * 4);
            *(float4*)(cp + c * 4) = make_float4(
                (o[c * 4 + 0] + p4.x) * inv, (o[c * 4 + 1] + p4.y) * inv,
                (o[c * 4 + 2] + p4.z) * inv, (o[c * 4 + 3] + p4.w) * inv);
        }
    }
    __syncthreads();

    // Coalesced attention-weight store: 4096 float4, 256 threads x 16.
    {
        float4* awp = (float4*)(AW + (long)(i * 10 + h) * 16384);
        #pragma unroll
        for (int e0 = 0; e0 < 16; e0++) {
            int e = tid + e0 * 256;
            int s = e >> 5;
            int l = e & 31;
            float4 v4 = *(const float4*)(es + s * 132 + l * 4);
            float iv = sinv[s];
            awp[e] = make_float4(v4.x * iv, v4.y * iv, v4.z * iv, v4.w * iv);
        }
    }
}

// ---------------------------------------------------------------------------
extern "C" void kernel_launch(void* const* d_in, const int* in_sizes, int n_in,
                              void* d_out, int out_size) {
    const float* x  = (const float*)d_in[0];
    const float* wq = (const float*)d_in[1];
    const float* wk = (const float*)d_in[2];
    const float* wv = (const float*)d_in[3];

    float* attn = (float*)d_out;                       // 1024*10*128*128
    float* out  = (float*)d_out + 167772160L;          // 131072*200

    float *gq, *gk, *gv, *gctx;
    __nv_bfloat16 *whi, *wlo;
    cudaGetSymbolAddress((void**)&gq,   g_q);
    cudaGetSymbolAddress((void**)&gk,   g_k);
    cudaGetSymbolAddress((void**)&gv,   g_v);
    cudaGetSymbolAddress((void**)&gctx, g_ctx);
    cudaGetSymbolAddress((void**)&whi,  g_whi);
    cudaGetSymbolAddress((void**)&wlo,  g_wlo);

    // 2560+2560+16896+128+128+2560 = 24832 floats = 99328 B
    const int AT_SMEM = 24832 * 4;
    cudaFuncSetAttribute(gemm_mma, cudaFuncAttributeMaxDynamicSharedMemorySize, GEMM_SMEM);
    cudaFuncSetAttribute(attn256,  cudaFuncAttributeMaxDynamicSharedMemorySize, AT_SMEM);

    const int WSZ = 208 * 256;

    conv_wt<<<208, 256>>>(wq, whi + 0 * WSZ, wlo + 0 * WSZ);
    conv_wt<<<208, 256>>>(wk, whi + 1 * WSZ, wlo + 1 * WSZ);
    conv_wt<<<208, 256>>>(wv, whi + 2 * WSZ, wlo + 2 * WSZ);

    gemm_mma<<<1024, 256, GEMM_SMEM>>>(x, whi + 0 * WSZ, wlo + 0 * WSZ, gq);
    gemm_mma<<<1024, 256, GEMM_SMEM>>>(x, whi + 1 * WSZ, wlo + 1 * WSZ, gk);
    gemm_mma<<<1024, 256, GEMM_SMEM>>>(x, whi + 2 * WSZ, wlo + 2 * WSZ, gv);

    attn256<<<dim3(1024, 10), 256, AT_SMEM>>>(gq, gk, gv, attn, gctx);

    gemm_mma<<<1024, 256, GEMM_SMEM>>>(gctx, whi + 0 * WSZ, wlo + 0 * WSZ, out);
}